// round 14
// baseline (speedup 1.0000x reference)
#include <cuda_runtime.h>

#define NT 256
#define TS 64           // tile size
#define KP 4            // tile-pairs per CTA

__device__ double       g_sum;
__device__ double       g_adj;
__device__ unsigned int g_cnt;

static __device__ __forceinline__ float sqa(float x) {
    float y; asm("sqrt.approx.f32 %0,%1;" : "=f"(y) : "f"(x)); return y;
}

extern __shared__ float smem_dyn[];
// layout (floats):
//   [0, KP*8*TS)                 : sJ   — j-side SoA (px,py,pz,pw,tx,ty,tz,tw per pair)
//   [KP*8*TS, +KP*2*TS*4)        : sI4  — i-side float4 constants (P rows, then T rows, per pair)
//   [.., +2*TS*(TS+1))           : d2s  — double-buffered transpose scratch (SCALAR access only)

// ---------------- symmetric multi-pair kernel (N % 64 == 0) ----------------
__global__ void __launch_bounds__(NT, 3)
pair_kernel(const float* __restrict__ preds,
            const float* __restrict__ targets,
            const float* __restrict__ adj,
            float* __restrict__ out,
            int N)
{
    const int b     = blockIdx.y;
    const int ntile = N / TS;
    const int PB    = ntile * (ntile + 1) / 2;
    const int p0    = blockIdx.x * KP;

    float*  sJ  = smem_dyn;                                  // KP*8*TS
    float4* sI4 = (float4*)(smem_dyn + KP * 8 * TS);         // KP*2*TS float4
    float*  d2s = smem_dyn + KP * 8 * TS + KP * 2 * TS * 4;  // 2*TS*(TS+1)

    __shared__ int    s_IJ[KP][2];
    __shared__ float2 wsum[NT / 32];

    const int tid = threadIdx.x;

    // ---- decode first pair (closed form + exact fixup), enumerate KP pairs ----
    int I0;
    {
        float nn = 2.f * ntile + 1.f;
        I0 = (int)((nn - sqrtf(fmaxf(nn * nn - 8.f * (float)p0, 0.f))) * 0.5f);
        if (I0 < 0) I0 = 0;
        if (I0 > ntile - 1) I0 = ntile - 1;
        while (I0 + 1 <= ntile - 1 &&
               (I0 + 1) * ntile - ((I0 + 1) * I0) / 2 <= p0) I0++;
        while (I0 > 0 && I0 * ntile - (I0 * (I0 - 1)) / 2 > p0) I0--;
    }
    int Jc = I0 + (p0 - (I0 * ntile - (I0 * (I0 - 1)) / 2));
    int Ic = I0;
    if (tid == 0) {
        int Ii = Ic, Jj = Jc;
        #pragma unroll
        for (int k = 0; k < KP; k++) {
            s_IJ[k][0] = Ii; s_IJ[k][1] = Jj;
            Jj++; if (Jj == ntile) { Ii++; Jj = Ii; }
        }
    }
    __syncthreads();

    // ---- stage all KP pairs: j-side as SoA, i-side as pre-scaled float4 rows ----
    for (int s = tid; s < KP * 2 * TS; s += NT) {
        int k    = s >> 7;
        int side = (s >> 6) & 1;
        int idx  = s & (TS - 1);
        if (p0 + k < PB) {
            int g = s_IJ[k][side] * TS + idx;
            const float* pb = preds   + ((size_t)b * N + g) * 3;
            const float* tb = targets + ((size_t)b * N + g) * 3;
            float x = pb[0], y = pb[1], z = pb[2];
            float u = tb[0], v = tb[1], w = tb[2];
            float pw = fmaf(x, x, fmaf(y, y, z * z));
            float tw = fmaf(u, u, fmaf(v, v, w * w));
            if (side == 0) {   // i-side: row constants (pre-scaled by -2)
                sI4[k * 2 * TS + idx]      = make_float4(-2.f * x, -2.f * y, -2.f * z, pw);
                sI4[k * 2 * TS + TS + idx] = make_float4(-2.f * u, -2.f * v, -2.f * w, tw);
            } else {           // j-side: SoA for vector LDS
                float* base = sJ + k * 8 * TS;
                base[0 * TS + idx] = x;  base[1 * TS + idx] = y;
                base[2 * TS + idx] = z;  base[3 * TS + idx] = pw;
                base[4 * TS + idx] = u;  base[5 * TS + idx] = v;
                base[6 * TS + idx] = w;  base[7 * TS + idx] = tw;
            }
        }
    }
    __syncthreads();

    const int jx = tid & 15;    // j-group: cols jx*4..+3
    const int iy = tid >> 4;    // i-group: rows iy*4..+3

    float acc = 0.f, accA = 0.f;
    const float* adjB = adj + (size_t)b * N * N;

    int I = Ic, J = Jc;
    #pragma unroll
    for (int k = 0; k < KP; k++) {
        if (p0 + k < PB) {
            const bool offd = (I != J);
            float* buf = d2s + (k & 1) * TS * (TS + 1);

            // adj[I,J] block (coalesced float4), issued before compute
            float4 aA[4];
            #pragma unroll
            for (int r = 0; r < 4; r++)
                aA[r] = *(const float4*)&adjB[(size_t)(I * TS + iy * 4 + r) * N + J * TS + jx * 4];

            // j-quad (vector LDS, 16B-aligned)
            const float* jb = sJ + k * 8 * TS + jx * 4;
            float4 jpx = *(const float4*)&jb[0 * TS];
            float4 jpy = *(const float4*)&jb[1 * TS];
            float4 jpz = *(const float4*)&jb[2 * TS];
            float4 jpw = *(const float4*)&jb[3 * TS];
            float4 jtx = *(const float4*)&jb[4 * TS];
            float4 jty = *(const float4*)&jb[5 * TS];
            float4 jtz = *(const float4*)&jb[6 * TS];
            float4 jtw = *(const float4*)&jb[7 * TS];
            const float px_[4] = {jpx.x, jpx.y, jpx.z, jpx.w};
            const float py_[4] = {jpy.x, jpy.y, jpy.z, jpy.w};
            const float pz_[4] = {jpz.x, jpz.y, jpz.z, jpz.w};
            const float pw_[4] = {jpw.x, jpw.y, jpw.z, jpw.w};
            const float tx_[4] = {jtx.x, jtx.y, jtx.z, jtx.w};
            const float ty_[4] = {jty.x, jty.y, jty.z, jty.w};
            const float tz_[4] = {jtz.x, jtz.y, jtz.z, jtz.w};
            const float tw_[4] = {jtw.x, jtw.y, jtw.z, jtw.w};

            // Phase A: d2 once; P/T read per-row from SMEM (broadcast LDS.128, not registers)
            #pragma unroll
            for (int r = 0; r < 4; r++) {
                float4 Pr = sI4[k * 2 * TS + iy * 4 + r];
                float4 Tr = sI4[k * 2 * TS + TS + iy * 4 + r];
                float d[4];
                #pragma unroll
                for (int q = 0; q < 4; q++) {
                    float sqp = fmaf(Pr.x, px_[q], fmaf(Pr.y, py_[q], fmaf(Pr.z, pz_[q], Pr.w + pw_[q])));
                    float sqt = fmaf(Tr.x, tx_[q], fmaf(Tr.y, ty_[q], fmaf(Tr.z, tz_[q], Tr.w + tw_[q])));
                    float rt  = sqa(fmaxf(sqp * sqt, 0.f));
                    d[q] = fmaf(-2.f, rt, sqp + sqt);      // (dp - dt)^2
                }
                acc  = fmaf(d[0], aA[r].x, fmaf(d[1], aA[r].y, fmaf(d[2], aA[r].z, fmaf(d[3], aA[r].w, acc))));
                accA += (aA[r].x + aA[r].y) + (aA[r].z + aA[r].w);
                #pragma unroll
                for (int q = 0; q < 4; q++) buf[(iy * 4 + r) * (TS + 1) + jx * 4 + q] = d[q];
            }

            // issue adj[J,I] loads NOW (independent of d2s): in flight across the barrier;
            // jquad registers are dead here, so aJ reuses them instead of raising the peak.
            float4 aJ[4];
            if (offd) {
                #pragma unroll
                for (int r = 0; r < 4; r++)
                    aJ[r] = *(const float4*)&adjB[(size_t)(J * TS + iy * 4 + r) * N + I * TS + jx * 4];
            }

            __syncthreads();   // d2s writes -> transposed reads (only barrier per pair)

            // Phase B: apply d2^T to adj[J,I]
            if (offd) {
                #pragma unroll
                for (int r = 0; r < 4; r++) {
                    float d0  = buf[(jx * 4 + 0) * (TS + 1) + iy * 4 + r];
                    float d1  = buf[(jx * 4 + 1) * (TS + 1) + iy * 4 + r];
                    float d2v = buf[(jx * 4 + 2) * (TS + 1) + iy * 4 + r];
                    float d3  = buf[(jx * 4 + 3) * (TS + 1) + iy * 4 + r];
                    acc  = fmaf(d0, aJ[r].x, fmaf(d1, aJ[r].y, fmaf(d2v, aJ[r].z, fmaf(d3, aJ[r].w, acc))));
                    accA += (aJ[r].x + aJ[r].y) + (aJ[r].z + aJ[r].w);
                }
            }
            // no trailing sync: next pair writes the other d2s buffer; its barrier
            // orders this pair's reads vs the pair-after-next's writes.
        }
        J++; if (J == ntile) { I++; J = I; }
    }

    // reduce + single-launch finalize
    #pragma unroll
    for (int off = 16; off > 0; off >>= 1) {
        acc  += __shfl_down_sync(0xffffffffu, acc,  off);
        accA += __shfl_down_sync(0xffffffffu, accA, off);
    }
    int wid = tid >> 5, lane = tid & 31;
    if (lane == 0) wsum[wid] = make_float2(acc, accA);
    __syncthreads();
    if (wid == 0) {
        float2 v = (lane < NT / 32) ? wsum[lane] : make_float2(0.f, 0.f);
        #pragma unroll
        for (int off = 4; off > 0; off >>= 1) {
            v.x += __shfl_down_sync(0xffffffffu, v.x, off);
            v.y += __shfl_down_sync(0xffffffffu, v.y, off);
        }
        if (lane == 0) {
            atomicAdd(&g_sum, (double)v.x);
            atomicAdd(&g_adj, (double)v.y);
            __threadfence();
            unsigned int nb  = gridDim.x * gridDim.y;
            unsigned int old = atomicAdd(&g_cnt, 1u);
            if (old % nb == nb - 1u) {
                __threadfence();
                double s = atomicAdd(&g_sum, 0.0);
                double n = atomicAdd(&g_adj, 0.0);
                out[0] = (float)(s / n);
                g_sum = 0.0;
                g_adj = 0.0;
            }
        }
    }
}

// ---------------- generic fallback (any N multiple of 4), R6 structure ----------------
__global__ void __launch_bounds__(NT, 2)
loss_generic(const float* __restrict__ preds,
             const float* __restrict__ targets,
             const float* __restrict__ adj,
             float* __restrict__ out,
             int N)
{
    float* s_raw = smem_dyn;
    const int b    = blockIdx.y;
    const int row0 = blockIdx.x * 16;
    float* spx = s_raw;        float* spy = spx + N;
    float* spz = spy + N;      float* spw = spz + N;
    float* stx = spw + N;      float* sty = stx + N;
    float* stz = sty + N;      float* stw = stz + N;
    {
        const float* pb = preds   + (size_t)b * N * 3;
        const float* tb = targets + (size_t)b * N * 3;
        for (int k = threadIdx.x; k < N; k += NT) {
            float x = pb[3*k], y = pb[3*k+1], z = pb[3*k+2];
            spx[k] = x; spy[k] = y; spz[k] = z; spw[k] = fmaf(x, x, fmaf(y, y, z*z));
            float u = tb[3*k], v = tb[3*k+1], w = tb[3*k+2];
            stx[k] = u; sty[k] = v; stz[k] = w; stw[k] = fmaf(u, u, fmaf(v, v, w*w));
        }
    }
    __syncthreads();
    float acc = 0.f, accA = 0.f;
    const int N4 = N >> 2;
    const float* adjB = adj + (size_t)b * N * N;
    for (int ig = 0; ig < 16; ig += 4) {
        const int rbase = row0 + ig;
        float4 P[4], T[4];
        #pragma unroll
        for (int r = 0; r < 4; r++) {
            int k = rbase + r;
            P[r] = make_float4(-2.f*spx[k], -2.f*spy[k], -2.f*spz[k], spw[k]);
            T[r] = make_float4(-2.f*stx[k], -2.f*sty[k], -2.f*stz[k], stw[k]);
        }
        const float4* adjR = (const float4*)(adjB + (size_t)rbase * N);
        for (int jv = threadIdx.x; jv < N4; jv += NT) {
            float4 jpx = ((const float4*)spx)[jv]; float4 jpy = ((const float4*)spy)[jv];
            float4 jpz = ((const float4*)spz)[jv]; float4 jpw = ((const float4*)spw)[jv];
            float4 jtx = ((const float4*)stx)[jv]; float4 jty = ((const float4*)sty)[jv];
            float4 jtz = ((const float4*)stz)[jv]; float4 jtw = ((const float4*)stw)[jv];
            const float px_[4] = {jpx.x, jpx.y, jpx.z, jpx.w};
            const float py_[4] = {jpy.x, jpy.y, jpy.z, jpy.w};
            const float pz_[4] = {jpz.x, jpz.y, jpz.z, jpz.w};
            const float pw_[4] = {jpw.x, jpw.y, jpw.z, jpw.w};
            const float tx_[4] = {jtx.x, jtx.y, jtx.z, jtx.w};
            const float ty_[4] = {jty.x, jty.y, jty.z, jty.w};
            const float tz_[4] = {jtz.x, jtz.y, jtz.z, jtz.w};
            const float tw_[4] = {jtw.x, jtw.y, jtw.z, jtw.w};
            #pragma unroll
            for (int r = 0; r < 4; r++) {
                float4 a = adjR[(size_t)r * N4 + jv];
                const float av[4] = {a.x, a.y, a.z, a.w};
                #pragma unroll
                for (int q = 0; q < 4; q++) {
                    float sqp = fmaf(P[r].x, px_[q], fmaf(P[r].y, py_[q], fmaf(P[r].z, pz_[q], P[r].w + pw_[q])));
                    float sqt = fmaf(T[r].x, tx_[q], fmaf(T[r].y, ty_[q], fmaf(T[r].z, tz_[q], T[r].w + tw_[q])));
                    float rt = sqa(fmaxf(sqp * sqt, 0.f));
                    acc = fmaf(fmaf(-2.f, rt, sqp + sqt), av[q], acc);
                }
                accA += (av[0] + av[1]) + (av[2] + av[3]);
            }
        }
    }
    #pragma unroll
    for (int off = 16; off > 0; off >>= 1) {
        acc  += __shfl_down_sync(0xffffffffu, acc,  off);
        accA += __shfl_down_sync(0xffffffffu, accA, off);
    }
    __shared__ float2 wsum[NT / 32];
    int wid = threadIdx.x >> 5, lane = threadIdx.x & 31;
    if (lane == 0) wsum[wid] = make_float2(acc, accA);
    __syncthreads();
    if (wid == 0) {
        float2 v = (lane < NT / 32) ? wsum[lane] : make_float2(0.f, 0.f);
        #pragma unroll
        for (int off = 4; off > 0; off >>= 1) {
            v.x += __shfl_down_sync(0xffffffffu, v.x, off);
            v.y += __shfl_down_sync(0xffffffffu, v.y, off);
        }
        if (lane == 0) {
            atomicAdd(&g_sum, (double)v.x);
            atomicAdd(&g_adj, (double)v.y);
            __threadfence();
            unsigned int nb  = gridDim.x * gridDim.y;
            unsigned int old = atomicAdd(&g_cnt, 1u);
            if (old % nb == nb - 1u) {
                __threadfence();
                double s = atomicAdd(&g_sum, 0.0);
                double n = atomicAdd(&g_adj, 0.0);
                out[0] = (float)(s / n);
                g_sum = 0.0; g_adj = 0.0;
            }
        }
    }
}

extern "C" void kernel_launch(void* const* d_in, const int* in_sizes, int n_in,
                              void* d_out, int out_size)
{
    const float* preds   = (const float*)d_in[0];
    const float* targets = (const float*)d_in[1];
    const float* adj     = (const float*)d_in[2];

    long long psz   = in_sizes[0];          // B*N*3
    long long adjsz = in_sizes[2];          // B*N*N
    int N = (int)(3LL * adjsz / psz);       // 2048
    int B = (int)(psz / (3LL * N));         // 8

    if (N % TS == 0) {
        int ntile = N / TS;
        int PB = ntile * (ntile + 1) / 2;
        size_t smem = (size_t)(KP * 8 * TS + KP * 2 * TS * 4 + 2 * TS * (TS + 1)) * sizeof(float);
        cudaFuncSetAttribute(pair_kernel, cudaFuncAttributeMaxDynamicSharedMemorySize, (int)smem);
        dim3 grid((PB + KP - 1) / KP, B);
        pair_kernel<<<grid, NT, smem>>>(preds, targets, adj, (float*)d_out, N);
    } else {
        size_t smem = (size_t)8 * N * sizeof(float);
        cudaFuncSetAttribute(loss_generic, cudaFuncAttributeMaxDynamicSharedMemorySize, (int)smem);
        dim3 grid(N / 16, B);
        loss_generic<<<grid, NT, smem>>>(preds, targets, adj, (float*)d_out, N);
    }
}

// round 15
// speedup vs baseline: 1.1482x; 1.1482x over previous
#include <cuda_runtime.h>

#define NT   256
#define TS   64          // tile size
#define KP   4           // tile-pairs per CTA
#define DSTR 68          // d2s row stride in floats: 68*4B=272 ≡ 0 mod 16 -> float4-safe both phases

__device__ double       g_sum;
__device__ double       g_adj;
__device__ unsigned int g_cnt;

static __device__ __forceinline__ float sqa(float x) {
    float y; asm("sqrt.approx.f32 %0,%1;" : "=f"(y) : "f"(x)); return y;
}

extern __shared__ float smem_dyn[];
// pair kernel layout (floats):
//   [0, KP*2*8*TS)        : sP  — per pair, per side (I=0/J=1), 8 SoA comps (px,py,pz,pw,tx,ty,tz,tw)
//   [KP*2*8*TS, +2*TS*DSTR): d2s — double-buffered transpose scratch (vector access, stride 68)

// ---------------- symmetric multi-pair kernel (N % 64 == 0) ----------------
template <int NC>   // NC>0: compile-time N (immediate-offset addressing); NC==0: runtime N
__global__ void __launch_bounds__(NT, 2)
pair_kernel(const float* __restrict__ preds,
            const float* __restrict__ targets,
            const float* __restrict__ adj,
            float* __restrict__ out,
            int Nrt)
{
    const int N     = (NC > 0) ? NC : Nrt;
    const int b     = blockIdx.y;
    const int ntile = N / TS;
    const int PB    = ntile * (ntile + 1) / 2;
    const int p0    = blockIdx.x * KP;

    float* sP  = smem_dyn;                    // KP*2*8*TS floats
    float* d2s = smem_dyn + KP * 2 * 8 * TS;  // 2*TS*DSTR floats

    __shared__ int    s_IJ[KP][2];
    __shared__ float2 wsum[NT / 32];

    const int tid = threadIdx.x;

    // ---- decode first pair (closed form + exact fixup), enumerate KP pairs ----
    int I0;
    {
        float nn = 2.f * ntile + 1.f;
        I0 = (int)((nn - sqrtf(fmaxf(nn * nn - 8.f * (float)p0, 0.f))) * 0.5f);
        if (I0 < 0) I0 = 0;
        if (I0 > ntile - 1) I0 = ntile - 1;
        while (I0 + 1 <= ntile - 1 &&
               (I0 + 1) * ntile - ((I0 + 1) * I0) / 2 <= p0) I0++;
        while (I0 > 0 && I0 * ntile - (I0 * (I0 - 1)) / 2 > p0) I0--;
    }
    int Jc = I0 + (p0 - (I0 * ntile - (I0 * (I0 - 1)) / 2));
    int Ic = I0;
    if (tid == 0) {
        int Ii = Ic, Jj = Jc;
        #pragma unroll
        for (int k = 0; k < KP; k++) {
            s_IJ[k][0] = Ii; s_IJ[k][1] = Jj;
            Jj++; if (Jj == ntile) { Ii++; Jj = Ii; }
        }
    }
    __syncthreads();

    // ---- stage points for all KP pairs (SoA per pair/side) ----
    for (int s = tid; s < KP * 2 * TS; s += NT) {
        int k    = s >> 7;
        int side = (s >> 6) & 1;
        int idx  = s & (TS - 1);
        if (p0 + k < PB) {
            int g = s_IJ[k][side] * TS + idx;
            const float* pb = preds   + ((size_t)b * N + g) * 3;
            const float* tb = targets + ((size_t)b * N + g) * 3;
            float x = pb[0], y = pb[1], z = pb[2];
            float u = tb[0], v = tb[1], w = tb[2];
            float* base = sP + (k * 2 + side) * 8 * TS;
            base[0 * TS + idx] = x;  base[1 * TS + idx] = y;
            base[2 * TS + idx] = z;  base[3 * TS + idx] = fmaf(x, x, fmaf(y, y, z * z));
            base[4 * TS + idx] = u;  base[5 * TS + idx] = v;
            base[6 * TS + idx] = w;  base[7 * TS + idx] = fmaf(u, u, fmaf(v, v, w * w));
        }
    }
    __syncthreads();

    const int jx = tid & 15;    // j-group: cols jx*4..+3
    const int iy = tid >> 4;    // i-group: rows iy*4..+3

    float acc = 0.f, accA = 0.f;
    const float* adjB = adj + (size_t)b * N * N;

    int I = Ic, J = Jc;
    #pragma unroll
    for (int k = 0; k < KP; k++) {
        if (p0 + k < PB) {
            const bool offd = (I != J);
            float* buf  = d2s + (k & 1) * TS * DSTR;
            float* bufA = buf + (iy * 4) * DSTR + jx * 4;   // phase-A vector store base
            float* bufB = buf + (jx * 4) * DSTR + iy * 4;   // phase-B vector load base

            // per-pair base pointers: loads below use compile-time offsets (r*N) when NC>0
            const float* aAp = adjB + (size_t)(I * TS + iy * 4) * N + J * TS + jx * 4;
            const float* aJp = adjB + (size_t)(J * TS + iy * 4) * N + I * TS + jx * 4;

            float4 aA[4];
            #pragma unroll
            for (int r = 0; r < 4; r++)
                aA[r] = *(const float4*)(aAp + r * N);

            // i-row constants (pre-scaled by -2), broadcast scalar LDS
            const float* ib = sP + (k * 2 + 0) * 8 * TS;
            float4 P[4], T[4];
            #pragma unroll
            for (int r = 0; r < 4; r++) {
                int i = iy * 4 + r;
                P[r] = make_float4(-2.f * ib[0*TS+i], -2.f * ib[1*TS+i], -2.f * ib[2*TS+i], ib[3*TS+i]);
                T[r] = make_float4(-2.f * ib[4*TS+i], -2.f * ib[5*TS+i], -2.f * ib[6*TS+i], ib[7*TS+i]);
            }
            // j-quad (vector LDS, 16B-aligned)
            const float* jb = sP + (k * 2 + 1) * 8 * TS + jx * 4;
            float4 jpx = *(const float4*)&jb[0 * TS];
            float4 jpy = *(const float4*)&jb[1 * TS];
            float4 jpz = *(const float4*)&jb[2 * TS];
            float4 jpw = *(const float4*)&jb[3 * TS];
            float4 jtx = *(const float4*)&jb[4 * TS];
            float4 jty = *(const float4*)&jb[5 * TS];
            float4 jtz = *(const float4*)&jb[6 * TS];
            float4 jtw = *(const float4*)&jb[7 * TS];
            const float px_[4] = {jpx.x, jpx.y, jpx.z, jpx.w};
            const float py_[4] = {jpy.x, jpy.y, jpy.z, jpy.w};
            const float pz_[4] = {jpz.x, jpz.y, jpz.z, jpz.w};
            const float pw_[4] = {jpw.x, jpw.y, jpw.z, jpw.w};
            const float tx_[4] = {jtx.x, jtx.y, jtx.z, jtx.w};
            const float ty_[4] = {jty.x, jty.y, jty.z, jty.w};
            const float tz_[4] = {jtz.x, jtz.y, jtz.z, jtz.w};
            const float tw_[4] = {jtw.x, jtw.y, jtw.z, jtw.w};

            // Phase A: d2 once, apply adj[I,J], vector-store to d2s (stride 68 -> aligned)
            #pragma unroll
            for (int r = 0; r < 4; r++) {
                float d[4];
                #pragma unroll
                for (int q = 0; q < 4; q++) {
                    float sqp = fmaf(P[r].x, px_[q], fmaf(P[r].y, py_[q], fmaf(P[r].z, pz_[q], P[r].w + pw_[q])));
                    float sqt = fmaf(T[r].x, tx_[q], fmaf(T[r].y, ty_[q], fmaf(T[r].z, tz_[q], T[r].w + tw_[q])));
                    float rt  = sqa(fmaxf(sqp * sqt, 0.f));
                    d[q] = fmaf(-2.f, rt, sqp + sqt);      // (dp - dt)^2
                }
                acc  = fmaf(d[0], aA[r].x, fmaf(d[1], aA[r].y, fmaf(d[2], aA[r].z, fmaf(d[3], aA[r].w, acc))));
                accA += (aA[r].x + aA[r].y) + (aA[r].z + aA[r].w);
                *(float4*)(bufA + r * DSTR) = make_float4(d[0], d[1], d[2], d[3]);
            }

            // issue adj[J,I] now: jquad registers are dead, loads fly across the barrier
            float4 aJ[4];
            if (offd) {
                #pragma unroll
                for (int r = 0; r < 4; r++)
                    aJ[r] = *(const float4*)(aJp + r * N);
            }

            __syncthreads();   // d2s writes -> transposed reads (only barrier per pair)

            // Phase B: vector-load transposed columns, apply adj[J,I]
            if (offd) {
                float4 ld[4];
                #pragma unroll
                for (int q = 0; q < 4; q++)
                    ld[q] = *(const float4*)(bufB + q * DSTR);
                #pragma unroll
                for (int r = 0; r < 4; r++) {
                    float d0  = (&ld[0].x)[r];
                    float d1  = (&ld[1].x)[r];
                    float d2v = (&ld[2].x)[r];
                    float d3  = (&ld[3].x)[r];
                    acc  = fmaf(d0, aJ[r].x, fmaf(d1, aJ[r].y, fmaf(d2v, aJ[r].z, fmaf(d3, aJ[r].w, acc))));
                    accA += (aJ[r].x + aJ[r].y) + (aJ[r].z + aJ[r].w);
                }
            }
            // no trailing sync: next pair writes the other buffer; its barrier
            // orders this pair's reads vs the pair-after-next's writes.
        }
        J++; if (J == ntile) { I++; J = I; }
    }

    // reduce + single-launch finalize
    #pragma unroll
    for (int off = 16; off > 0; off >>= 1) {
        acc  += __shfl_down_sync(0xffffffffu, acc,  off);
        accA += __shfl_down_sync(0xffffffffu, accA, off);
    }
    int wid = tid >> 5, lane = tid & 31;
    if (lane == 0) wsum[wid] = make_float2(acc, accA);
    __syncthreads();
    if (wid == 0) {
        float2 v = (lane < NT / 32) ? wsum[lane] : make_float2(0.f, 0.f);
        #pragma unroll
        for (int off = 4; off > 0; off >>= 1) {
            v.x += __shfl_down_sync(0xffffffffu, v.x, off);
            v.y += __shfl_down_sync(0xffffffffu, v.y, off);
        }
        if (lane == 0) {
            atomicAdd(&g_sum, (double)v.x);
            atomicAdd(&g_adj, (double)v.y);
            __threadfence();
            unsigned int nb  = gridDim.x * gridDim.y;
            unsigned int old = atomicAdd(&g_cnt, 1u);
            if (old % nb == nb - 1u) {
                __threadfence();
                double s = atomicAdd(&g_sum, 0.0);
                double n = atomicAdd(&g_adj, 0.0);
                out[0] = (float)(s / n);
                g_sum = 0.0;
                g_adj = 0.0;
            }
        }
    }
}

// ---------------- generic fallback (any N multiple of 4), R6 structure ----------------
__global__ void __launch_bounds__(NT, 2)
loss_generic(const float* __restrict__ preds,
             const float* __restrict__ targets,
             const float* __restrict__ adj,
             float* __restrict__ out,
             int N)
{
    float* s_raw = smem_dyn;
    const int b    = blockIdx.y;
    const int row0 = blockIdx.x * 16;
    float* spx = s_raw;        float* spy = spx + N;
    float* spz = spy + N;      float* spw = spz + N;
    float* stx = spw + N;      float* sty = stx + N;
    float* stz = sty + N;      float* stw = stz + N;
    {
        const float* pb = preds   + (size_t)b * N * 3;
        const float* tb = targets + (size_t)b * N * 3;
        for (int k = threadIdx.x; k < N; k += NT) {
            float x = pb[3*k], y = pb[3*k+1], z = pb[3*k+2];
            spx[k] = x; spy[k] = y; spz[k] = z; spw[k] = fmaf(x, x, fmaf(y, y, z*z));
            float u = tb[3*k], v = tb[3*k+1], w = tb[3*k+2];
            stx[k] = u; sty[k] = v; stz[k] = w; stw[k] = fmaf(u, u, fmaf(v, v, w*w));
        }
    }
    __syncthreads();
    float acc = 0.f, accA = 0.f;
    const int N4 = N >> 2;
    const float* adjB = adj + (size_t)b * N * N;
    for (int ig = 0; ig < 16; ig += 4) {
        const int rbase = row0 + ig;
        float4 P[4], T[4];
        #pragma unroll
        for (int r = 0; r < 4; r++) {
            int k = rbase + r;
            P[r] = make_float4(-2.f*spx[k], -2.f*spy[k], -2.f*spz[k], spw[k]);
            T[r] = make_float4(-2.f*stx[k], -2.f*sty[k], -2.f*stz[k], stw[k]);
        }
        const float4* adjR = (const float4*)(adjB + (size_t)rbase * N);
        for (int jv = threadIdx.x; jv < N4; jv += NT) {
            float4 jpx = ((const float4*)spx)[jv]; float4 jpy = ((const float4*)spy)[jv];
            float4 jpz = ((const float4*)spz)[jv]; float4 jpw = ((const float4*)spw)[jv];
            float4 jtx = ((const float4*)stx)[jv]; float4 jty = ((const float4*)sty)[jv];
            float4 jtz = ((const float4*)stz)[jv]; float4 jtw = ((const float4*)stw)[jv];
            const float px_[4] = {jpx.x, jpx.y, jpx.z, jpx.w};
            const float py_[4] = {jpy.x, jpy.y, jpy.z, jpy.w};
            const float pz_[4] = {jpz.x, jpz.y, jpz.z, jpz.w};
            const float pw_[4] = {jpw.x, jpw.y, jpw.z, jpw.w};
            const float tx_[4] = {jtx.x, jtx.y, jtx.z, jtx.w};
            const float ty_[4] = {jty.x, jty.y, jty.z, jty.w};
            const float tz_[4] = {jtz.x, jtz.y, jtz.z, jtz.w};
            const float tw_[4] = {jtw.x, jtw.y, jtw.z, jtw.w};
            #pragma unroll
            for (int r = 0; r < 4; r++) {
                float4 a = adjR[(size_t)r * N4 + jv];
                const float av[4] = {a.x, a.y, a.z, a.w};
                #pragma unroll
                for (int q = 0; q < 4; q++) {
                    float sqp = fmaf(P[r].x, px_[q], fmaf(P[r].y, py_[q], fmaf(P[r].z, pz_[q], P[r].w + pw_[q])));
                    float sqt = fmaf(T[r].x, tx_[q], fmaf(T[r].y, ty_[q], fmaf(T[r].z, tz_[q], T[r].w + tw_[q])));
                    float rt = sqa(fmaxf(sqp * sqt, 0.f));
                    acc = fmaf(fmaf(-2.f, rt, sqp + sqt), av[q], acc);
                }
                accA += (av[0] + av[1]) + (av[2] + av[3]);
            }
        }
    }
    #pragma unroll
    for (int off = 16; off > 0; off >>= 1) {
        acc  += __shfl_down_sync(0xffffffffu, acc,  off);
        accA += __shfl_down_sync(0xffffffffu, accA, off);
    }
    __shared__ float2 wsum[NT / 32];
    int wid = threadIdx.x >> 5, lane = threadIdx.x & 31;
    if (lane == 0) wsum[wid] = make_float2(acc, accA);
    __syncthreads();
    if (wid == 0) {
        float2 v = (lane < NT / 32) ? wsum[lane] : make_float2(0.f, 0.f);
        #pragma unroll
        for (int off = 4; off > 0; off >>= 1) {
            v.x += __shfl_down_sync(0xffffffffu, v.x, off);
            v.y += __shfl_down_sync(0xffffffffu, v.y, off);
        }
        if (lane == 0) {
            atomicAdd(&g_sum, (double)v.x);
            atomicAdd(&g_adj, (double)v.y);
            __threadfence();
            unsigned int nb  = gridDim.x * gridDim.y;
            unsigned int old = atomicAdd(&g_cnt, 1u);
            if (old % nb == nb - 1u) {
                __threadfence();
                double s = atomicAdd(&g_sum, 0.0);
                double n = atomicAdd(&g_adj, 0.0);
                out[0] = (float)(s / n);
                g_sum = 0.0; g_adj = 0.0;
            }
        }
    }
}

extern "C" void kernel_launch(void* const* d_in, const int* in_sizes, int n_in,
                              void* d_out, int out_size)
{
    const float* preds   = (const float*)d_in[0];
    const float* targets = (const float*)d_in[1];
    const float* adj     = (const float*)d_in[2];

    long long psz   = in_sizes[0];          // B*N*3
    long long adjsz = in_sizes[2];          // B*N*N
    int N = (int)(3LL * adjsz / psz);       // 2048
    int B = (int)(psz / (3LL * N));         // 8

    if (N % TS == 0) {
        int ntile = N / TS;
        int PB = ntile * (ntile + 1) / 2;
        size_t smem = (size_t)(KP * 2 * 8 * TS + 2 * TS * DSTR) * sizeof(float);  // ~51.2 KB
        dim3 grid((PB + KP - 1) / KP, B);
        if (N == 2048) {
            cudaFuncSetAttribute(pair_kernel<2048>, cudaFuncAttributeMaxDynamicSharedMemorySize, (int)smem);
            pair_kernel<2048><<<grid, NT, smem>>>(preds, targets, adj, (float*)d_out, N);
        } else {
            cudaFuncSetAttribute(pair_kernel<0>, cudaFuncAttributeMaxDynamicSharedMemorySize, (int)smem);
            pair_kernel<0><<<grid, NT, smem>>>(preds, targets, adj, (float*)d_out, N);
        }
    } else {
        size_t smem = (size_t)8 * N * sizeof(float);
        cudaFuncSetAttribute(loss_generic, cudaFuncAttributeMaxDynamicSharedMemorySize, (int)smem);
        dim3 grid(N / 16, B);
        loss_generic<<<grid, NT, smem>>>(preds, targets, adj, (float*)d_out, N);
    }
}

// round 16
// speedup vs baseline: 1.1960x; 1.0416x over previous
#include <cuda_runtime.h>

#define NT   256
#define TS   64          // tile size
#define KP   4           // tile-pairs per CTA
#define DSTR 68          // d2s row stride in floats: 272B ≡ 0 mod 16 -> float4-safe both phases

__device__ double       g_sum;
__device__ double       g_adj;
__device__ unsigned int g_cnt;

static __device__ __forceinline__ float sqa(float x) {
    float y; asm("sqrt.approx.f32 %0,%1;" : "=f"(y) : "f"(x)); return y;
}

extern __shared__ float smem_dyn[];
// pair kernel layout (floats):
//   [0, KP*2*8*TS)         : sP  — per pair, per side (I=0/J=1), 8 SoA comps
//                             I-side stored PRE-NEGATED: (-2x,-2y,-2z,pw,-2u,-2v,-2w,tw)
//   [KP*2*8*TS, +2*TS*DSTR): d2s — double-buffered transpose scratch (vector, stride 68)

// ---------------- symmetric multi-pair kernel (N % 64 == 0) ----------------
template <int NC>   // NC>0: compile-time N (immediate-offset addressing); NC==0: runtime N
__global__ void __launch_bounds__(NT, 2)
pair_kernel(const float* __restrict__ preds,
            const float* __restrict__ targets,
            const float* __restrict__ adj,
            float* __restrict__ out,
            int Nrt)
{
    const int N     = (NC > 0) ? NC : Nrt;
    const int b     = blockIdx.y;
    const int ntile = N / TS;
    const int PB    = ntile * (ntile + 1) / 2;
    const int p0    = blockIdx.x * KP;

    float* sP  = smem_dyn;                    // KP*2*8*TS floats
    float* d2s = smem_dyn + KP * 2 * 8 * TS;  // 2*TS*DSTR floats

    __shared__ int    s_IJ[KP][2];
    __shared__ float2 wsum[NT / 32];

    const int tid = threadIdx.x;

    // ---- decode first pair (closed form + exact fixup), enumerate KP pairs ----
    int I0;
    {
        float nn = 2.f * ntile + 1.f;
        I0 = (int)((nn - sqrtf(fmaxf(nn * nn - 8.f * (float)p0, 0.f))) * 0.5f);
        if (I0 < 0) I0 = 0;
        if (I0 > ntile - 1) I0 = ntile - 1;
        while (I0 + 1 <= ntile - 1 &&
               (I0 + 1) * ntile - ((I0 + 1) * I0) / 2 <= p0) I0++;
        while (I0 > 0 && I0 * ntile - (I0 * (I0 - 1)) / 2 > p0) I0--;
    }
    int Jc = I0 + (p0 - (I0 * ntile - (I0 * (I0 - 1)) / 2));
    int Ic = I0;
    if (tid == 0) {
        int Ii = Ic, Jj = Jc;
        #pragma unroll
        for (int k = 0; k < KP; k++) {
            s_IJ[k][0] = Ii; s_IJ[k][1] = Jj;
            Jj++; if (Jj == ntile) { Ii++; Jj = Ii; }
        }
    }
    __syncthreads();

    // ---- stage points for all KP pairs (SoA per pair/side; I-side pre-negated) ----
    for (int s = tid; s < KP * 2 * TS; s += NT) {
        int k    = s >> 7;
        int side = (s >> 6) & 1;
        int idx  = s & (TS - 1);
        if (p0 + k < PB) {
            int g = s_IJ[k][side] * TS + idx;
            const float* pb = preds   + ((size_t)b * N + g) * 3;
            const float* tb = targets + ((size_t)b * N + g) * 3;
            float x = pb[0], y = pb[1], z = pb[2];
            float u = tb[0], v = tb[1], w = tb[2];
            float pw = fmaf(x, x, fmaf(y, y, z * z));
            float tw = fmaf(u, u, fmaf(v, v, w * w));
            float* base = sP + (k * 2 + side) * 8 * TS;
            if (side == 0) {   // I-side: pre-negated row constants
                base[0 * TS + idx] = -2.f * x;  base[1 * TS + idx] = -2.f * y;
                base[2 * TS + idx] = -2.f * z;  base[3 * TS + idx] = pw;
                base[4 * TS + idx] = -2.f * u;  base[5 * TS + idx] = -2.f * v;
                base[6 * TS + idx] = -2.f * w;  base[7 * TS + idx] = tw;
            } else {           // J-side: raw SoA
                base[0 * TS + idx] = x;  base[1 * TS + idx] = y;
                base[2 * TS + idx] = z;  base[3 * TS + idx] = pw;
                base[4 * TS + idx] = u;  base[5 * TS + idx] = v;
                base[6 * TS + idx] = w;  base[7 * TS + idx] = tw;
            }
        }
    }
    __syncthreads();

    const int jx = tid & 15;    // j-group: cols jx*4..+3
    const int iy = tid >> 4;    // i-group: rows iy*4..+3

    float acc = 0.f, accA = 0.f;
    const float* adjB = adj + (size_t)b * N * N;

    int I = Ic, J = Jc;

    // ---- preload adj[I,J] for pair 0 (software pipeline prologue) ----
    float4 aA[4];
    if (p0 < PB) {
        const float* aAp = adjB + (size_t)(I * TS + iy * 4) * N + J * TS + jx * 4;
        #pragma unroll
        for (int r = 0; r < 4; r++) aA[r] = *(const float4*)(aAp + r * N);
    }

    #pragma unroll
    for (int k = 0; k < KP; k++) {
        int nI = I, nJ = J + 1; if (nJ == ntile) { nI++; nJ = nI; }

        if (p0 + k < PB) {
            const bool offd = (I != J);
            float* buf  = d2s + (k & 1) * TS * DSTR;
            float* bufA = buf + (iy * 4) * DSTR + jx * 4;
            float* bufB = buf + (jx * 4) * DSTR + iy * 4;

            // i-row constants: pre-negated, pure scalar LDS (no FMULs)
            const float* ib = sP + (k * 2 + 0) * 8 * TS;
            float4 P[4], T[4];
            #pragma unroll
            for (int r = 0; r < 4; r++) {
                int i = iy * 4 + r;
                P[r] = make_float4(ib[0*TS+i], ib[1*TS+i], ib[2*TS+i], ib[3*TS+i]);
                T[r] = make_float4(ib[4*TS+i], ib[5*TS+i], ib[6*TS+i], ib[7*TS+i]);
            }
            // j-quad (vector LDS, 16B-aligned)
            const float* jb = sP + (k * 2 + 1) * 8 * TS + jx * 4;
            float4 jpx = *(const float4*)&jb[0 * TS];
            float4 jpy = *(const float4*)&jb[1 * TS];
            float4 jpz = *(const float4*)&jb[2 * TS];
            float4 jpw = *(const float4*)&jb[3 * TS];
            float4 jtx = *(const float4*)&jb[4 * TS];
            float4 jty = *(const float4*)&jb[5 * TS];
            float4 jtz = *(const float4*)&jb[6 * TS];
            float4 jtw = *(const float4*)&jb[7 * TS];
            const float px_[4] = {jpx.x, jpx.y, jpx.z, jpx.w};
            const float py_[4] = {jpy.x, jpy.y, jpy.z, jpy.w};
            const float pz_[4] = {jpz.x, jpz.y, jpz.z, jpz.w};
            const float pw_[4] = {jpw.x, jpw.y, jpw.z, jpw.w};
            const float tx_[4] = {jtx.x, jtx.y, jtx.z, jtx.w};
            const float ty_[4] = {jty.x, jty.y, jty.z, jty.w};
            const float tz_[4] = {jtz.x, jtz.y, jtz.z, jtz.w};
            const float tw_[4] = {jtw.x, jtw.y, jtw.z, jtw.w};

            // Phase A: d2 once, apply adj[I,J] (aA already resident), vector-store d2s
            #pragma unroll
            for (int r = 0; r < 4; r++) {
                float d[4];
                #pragma unroll
                for (int q = 0; q < 4; q++) {
                    float sqp = fmaf(P[r].x, px_[q], fmaf(P[r].y, py_[q], fmaf(P[r].z, pz_[q], P[r].w + pw_[q])));
                    float sqt = fmaf(T[r].x, tx_[q], fmaf(T[r].y, ty_[q], fmaf(T[r].z, tz_[q], T[r].w + tw_[q])));
                    float rt  = sqa(fmaxf(sqp * sqt, 0.f));
                    d[q] = fmaf(-2.f, rt, sqp + sqt);      // (dp - dt)^2
                }
                acc  = fmaf(d[0], aA[r].x, fmaf(d[1], aA[r].y, fmaf(d[2], aA[r].z, fmaf(d[3], aA[r].w, acc))));
                accA += (aA[r].x + aA[r].y) + (aA[r].z + aA[r].w);
                *(float4*)(bufA + r * DSTR) = make_float4(d[0], d[1], d[2], d[3]);
            }

            // issue adj[J,I] for THIS pair (needed right after barrier)
            float4 aJ[4];
            if (offd) {
                const float* aJp = adjB + (size_t)(J * TS + iy * 4) * N + I * TS + jx * 4;
                #pragma unroll
                for (int r = 0; r < 4; r++) aJ[r] = *(const float4*)(aJp + r * N);
            }

            // prefetch adj[I',J'] for NEXT pair — aA registers are dead here,
            // loads cover phase B + barrier + next pair's setup
            if (k + 1 < KP && p0 + k + 1 < PB) {
                const float* aAn = adjB + (size_t)(nI * TS + iy * 4) * N + nJ * TS + jx * 4;
                #pragma unroll
                for (int r = 0; r < 4; r++) aA[r] = *(const float4*)(aAn + r * N);
            }

            __syncthreads();   // d2s writes -> transposed reads (only barrier per pair)

            // Phase B: vector-load transposed columns, apply adj[J,I]
            if (offd) {
                float4 ld[4];
                #pragma unroll
                for (int q = 0; q < 4; q++)
                    ld[q] = *(const float4*)(bufB + q * DSTR);
                #pragma unroll
                for (int r = 0; r < 4; r++) {
                    float d0  = (&ld[0].x)[r];
                    float d1  = (&ld[1].x)[r];
                    float d2v = (&ld[2].x)[r];
                    float d3  = (&ld[3].x)[r];
                    acc  = fmaf(d0, aJ[r].x, fmaf(d1, aJ[r].y, fmaf(d2v, aJ[r].z, fmaf(d3, aJ[r].w, acc))));
                    accA += (aJ[r].x + aJ[r].y) + (aJ[r].z + aJ[r].w);
                }
            }
        }
        I = nI; J = nJ;
    }

    // reduce + single-launch finalize
    #pragma unroll
    for (int off = 16; off > 0; off >>= 1) {
        acc  += __shfl_down_sync(0xffffffffu, acc,  off);
        accA += __shfl_down_sync(0xffffffffu, accA, off);
    }
    int wid = tid >> 5, lane = tid & 31;
    if (lane == 0) wsum[wid] = make_float2(acc, accA);
    __syncthreads();
    if (wid == 0) {
        float2 v = (lane < NT / 32) ? wsum[lane] : make_float2(0.f, 0.f);
        #pragma unroll
        for (int off = 4; off > 0; off >>= 1) {
            v.x += __shfl_down_sync(0xffffffffu, v.x, off);
            v.y += __shfl_down_sync(0xffffffffu, v.y, off);
        }
        if (lane == 0) {
            atomicAdd(&g_sum, (double)v.x);
            atomicAdd(&g_adj, (double)v.y);
            __threadfence();
            unsigned int nb  = gridDim.x * gridDim.y;
            unsigned int old = atomicAdd(&g_cnt, 1u);
            if (old % nb == nb - 1u) {
                __threadfence();
                double s = atomicAdd(&g_sum, 0.0);
                double n = atomicAdd(&g_adj, 0.0);
                out[0] = (float)(s / n);
                g_sum = 0.0;
                g_adj = 0.0;
            }
        }
    }
}

// ---------------- generic fallback (any N multiple of 4), R6 structure ----------------
__global__ void __launch_bounds__(NT, 2)
loss_generic(const float* __restrict__ preds,
             const float* __restrict__ targets,
             const float* __restrict__ adj,
             float* __restrict__ out,
             int N)
{
    float* s_raw = smem_dyn;
    const int b    = blockIdx.y;
    const int row0 = blockIdx.x * 16;
    float* spx = s_raw;        float* spy = spx + N;
    float* spz = spy + N;      float* spw = spz + N;
    float* stx = spw + N;      float* sty = stx + N;
    float* stz = sty + N;      float* stw = stz + N;
    {
        const float* pb = preds   + (size_t)b * N * 3;
        const float* tb = targets + (size_t)b * N * 3;
        for (int k = threadIdx.x; k < N; k += NT) {
            float x = pb[3*k], y = pb[3*k+1], z = pb[3*k+2];
            spx[k] = x; spy[k] = y; spz[k] = z; spw[k] = fmaf(x, x, fmaf(y, y, z*z));
            float u = tb[3*k], v = tb[3*k+1], w = tb[3*k+2];
            stx[k] = u; sty[k] = v; stz[k] = w; stw[k] = fmaf(u, u, fmaf(v, v, w*w));
        }
    }
    __syncthreads();
    float acc = 0.f, accA = 0.f;
    const int N4 = N >> 2;
    const float* adjB = adj + (size_t)b * N * N;
    for (int ig = 0; ig < 16; ig += 4) {
        const int rbase = row0 + ig;
        float4 P[4], T[4];
        #pragma unroll
        for (int r = 0; r < 4; r++) {
            int k = rbase + r;
            P[r] = make_float4(-2.f*spx[k], -2.f*spy[k], -2.f*spz[k], spw[k]);
            T[r] = make_float4(-2.f*stx[k], -2.f*sty[k], -2.f*stz[k], stw[k]);
        }
        const float4* adjR = (const float4*)(adjB + (size_t)rbase * N);
        for (int jv = threadIdx.x; jv < N4; jv += NT) {
            float4 jpx = ((const float4*)spx)[jv]; float4 jpy = ((const float4*)spy)[jv];
            float4 jpz = ((const float4*)spz)[jv]; float4 jpw = ((const float4*)spw)[jv];
            float4 jtx = ((const float4*)stx)[jv]; float4 jty = ((const float4*)sty)[jv];
            float4 jtz = ((const float4*)stz)[jv]; float4 jtw = ((const float4*)stw)[jv];
            const float px_[4] = {jpx.x, jpx.y, jpx.z, jpx.w};
            const float py_[4] = {jpy.x, jpy.y, jpy.z, jpy.w};
            const float pz_[4] = {jpz.x, jpz.y, jpz.z, jpz.w};
            const float pw_[4] = {jpw.x, jpw.y, jpw.z, jpw.w};
            const float tx_[4] = {jtx.x, jtx.y, jtx.z, jtx.w};
            const float ty_[4] = {jty.x, jty.y, jty.z, jty.w};
            const float tz_[4] = {jtz.x, jtz.y, jtz.z, jtz.w};
            const float tw_[4] = {jtw.x, jtw.y, jtw.z, jtw.w};
            #pragma unroll
            for (int r = 0; r < 4; r++) {
                float4 a = adjR[(size_t)r * N4 + jv];
                const float av[4] = {a.x, a.y, a.z, a.w};
                #pragma unroll
                for (int q = 0; q < 4; q++) {
                    float sqp = fmaf(P[r].x, px_[q], fmaf(P[r].y, py_[q], fmaf(P[r].z, pz_[q], P[r].w + pw_[q])));
                    float sqt = fmaf(T[r].x, tx_[q], fmaf(T[r].y, ty_[q], fmaf(T[r].z, tz_[q], T[r].w + tw_[q])));
                    float rt = sqa(fmaxf(sqp * sqt, 0.f));
                    acc = fmaf(fmaf(-2.f, rt, sqp + sqt), av[q], acc);
                }
                accA += (av[0] + av[1]) + (av[2] + av[3]);
            }
        }
    }
    #pragma unroll
    for (int off = 16; off > 0; off >>= 1) {
        acc  += __shfl_down_sync(0xffffffffu, acc,  off);
        accA += __shfl_down_sync(0xffffffffu, accA, off);
    }
    __shared__ float2 wsum[NT / 32];
    int wid = threadIdx.x >> 5, lane = threadIdx.x & 31;
    if (lane == 0) wsum[wid] = make_float2(acc, accA);
    __syncthreads();
    if (wid == 0) {
        float2 v = (lane < NT / 32) ? wsum[lane] : make_float2(0.f, 0.f);
        #pragma unroll
        for (int off = 4; off > 0; off >>= 1) {
            v.x += __shfl_down_sync(0xffffffffu, v.x, off);
            v.y += __shfl_down_sync(0xffffffffu, v.y, off);
        }
        if (lane == 0) {
            atomicAdd(&g_sum, (double)v.x);
            atomicAdd(&g_adj, (double)v.y);
            __threadfence();
            unsigned int nb  = gridDim.x * gridDim.y;
            unsigned int old = atomicAdd(&g_cnt, 1u);
            if (old % nb == nb - 1u) {
                __threadfence();
                double s = atomicAdd(&g_sum, 0.0);
                double n = atomicAdd(&g_adj, 0.0);
                out[0] = (float)(s / n);
                g_sum = 0.0; g_adj = 0.0;
            }
        }
    }
}

extern "C" void kernel_launch(void* const* d_in, const int* in_sizes, int n_in,
                              void* d_out, int out_size)
{
    const float* preds   = (const float*)d_in[0];
    const float* targets = (const float*)d_in[1];
    const float* adj     = (const float*)d_in[2];

    long long psz   = in_sizes[0];          // B*N*3
    long long adjsz = in_sizes[2];          // B*N*N
    int N = (int)(3LL * adjsz / psz);       // 2048
    int B = (int)(psz / (3LL * N));         // 8

    if (N % TS == 0) {
        int ntile = N / TS;
        int PB = ntile * (ntile + 1) / 2;
        size_t smem = (size_t)(KP * 2 * 8 * TS + 2 * TS * DSTR) * sizeof(float);  // ~51.2 KB
        dim3 grid((PB + KP - 1) / KP, B);
        if (N == 2048) {
            cudaFuncSetAttribute(pair_kernel<2048>, cudaFuncAttributeMaxDynamicSharedMemorySize, (int)smem);
            pair_kernel<2048><<<grid, NT, smem>>>(preds, targets, adj, (float*)d_out, N);
        } else {
            cudaFuncSetAttribute(pair_kernel<0>, cudaFuncAttributeMaxDynamicSharedMemorySize, (int)smem);
            pair_kernel<0><<<grid, NT, smem>>>(preds, targets, adj, (float*)d_out, N);
        }
    } else {
        size_t smem = (size_t)8 * N * sizeof(float);
        cudaFuncSetAttribute(loss_generic, cudaFuncAttributeMaxDynamicSharedMemorySize, (int)smem);
        dim3 grid(N / 16, B);
        loss_generic<<<grid, NT, smem>>>(preds, targets, adj, (float*)d_out, N);
    }
}